// round 13
// baseline (speedup 1.0000x reference)
#include <cuda_runtime.h>
#include <cstdint>
#include <math.h>

#define B_ 256
#define T_ 512
#define I_ 128
#define H_ 256

typedef unsigned long long ull;

// Scratch (static device globals — no dynamic allocation allowed).
__device__ float g_xw[(size_t)B_ * T_ * H_];   // [B][T][H] input projection + bias
__device__ float g_h[B_ * H_];                 // final hidden state
__device__ ull   g_wpack[I_ * (H_ / 2)];       // W_ih packed: [k][j2] = {W[2j2][k], W[2j2+1][k]}

// ---------------------------------------------------------------------------
// helpers
// ---------------------------------------------------------------------------
__device__ __forceinline__ void fma2(ull& acc, ull a, ull b) {
    asm("fma.rn.f32x2 %0, %1, %2, %0;" : "+l"(acc) : "l"(a), "l"(b));
}

__device__ __forceinline__ float unpack_sum(ull v) {
    float lo, hi;
    asm("mov.b64 {%0,%1}, %2;" : "=f"(lo), "=f"(hi) : "l"(v));
    return lo + hi;
}

__device__ __forceinline__ float2 unpack2(ull v) {
    float2 r;
    asm("mov.b64 {%0,%1}, %2;" : "=f"(r.x), "=f"(r.y) : "l"(v));
    return r;
}

__device__ __forceinline__ ull pack2(float a, float b) {
    ull u;
    asm("mov.b64 %0,{%1,%2};" : "=l"(u) : "f"(a), "f"(b));
    return u;
}

__device__ __forceinline__ ull dup1(float a) {
    ull u;
    asm("mov.b64 %0,{%1,%1};" : "=l"(u) : "f"(a));
    return u;
}

// tanh(x) = 1 - 2/(e^{2x}+1) via ex2/rcp approx. Branch-free, inf-safe.
__device__ __forceinline__ float ftanh(float x) {
    float e;
    asm("ex2.approx.f32 %0, %1;" : "=f"(e) : "f"(x * 2.8853900817779268f));
    float r;
    asm("rcp.approx.f32 %0, %1;" : "=f"(r) : "f"(e + 1.0f));
    return fmaf(-2.0f, r, 1.0f);
}

// ---------------------------------------------------------------------------
// Phase 0: pack W_ih k-major with j-pairs
// ---------------------------------------------------------------------------
__global__ void __launch_bounds__(256)
wpack_kernel(const float* __restrict__ Wih) {
    int t = blockIdx.x * 256 + threadIdx.x;   // 16384 total
    int j2 = t & 127, k = t >> 7;
    float a = __ldg(Wih + (2 * j2) * I_ + k);
    float b = __ldg(Wih + (2 * j2 + 1) * I_ + k);
    g_wpack[k * 128 + j2] = pack2(a, b);
}

// ---------------------------------------------------------------------------
// Phase 1: register-tiled f32x2 GEMM (unchanged)
// ---------------------------------------------------------------------------
__global__ void __launch_bounds__(256, 1)
xw_kernel(const float* __restrict__ x,
          const float* __restrict__ bih, const float* __restrict__ bhh) {
    extern __shared__ unsigned char smem_raw[];
    ull* xs = (ull*)smem_raw;                       // [r][k] dup, 128KB
    ull* ws = (ull*)(smem_raw + 128 * 128 * 8);     // [k][j2l], 64KB

    const int tid = threadIdx.x;
    const int jt  = blockIdx.x & 1;
    const int rt  = blockIdx.x >> 1;
    const int tx  = tid & 15;
    const int ty  = tid >> 4;

    {
        const float4* xg = (const float4*)(x + (size_t)rt * 128 * I_);
        for (int i = 0; i < 16; ++i) {
            int lin = tid + i * 256;
            float4 v = __ldg(xg + lin);
            int r = lin >> 5, kc = lin & 31;
            ulonglong2* d = (ulonglong2*)(xs + r * 128 + kc * 4);
            ulonglong2 u0; u0.x = dup1(v.x); u0.y = dup1(v.y);
            ulonglong2 u1; u1.x = dup1(v.z); u1.y = dup1(v.w);
            d[0] = u0; d[1] = u1;
        }
    }
    {
        const ulonglong2* wg = (const ulonglong2*)g_wpack;
        ulonglong2* wd = (ulonglong2*)ws;
        for (int i = 0; i < 16; ++i) {
            int lin = tid + i * 256;
            int k = lin >> 5, c = lin & 31;
            wd[k * 32 + c] = __ldg(wg + k * 64 + jt * 32 + c);
        }
    }
    __syncthreads();

    ull acc[8][4];
#pragma unroll
    for (int r = 0; r < 8; ++r)
#pragma unroll
        for (int j = 0; j < 4; ++j) acc[r][j] = 0ull;

    const ull* xrow = xs + (ty * 8) * 128;
    const ull* wcol = ws + tx;

#pragma unroll 4
    for (int k = 0; k < 128; ++k) {
        ull wv[4];
#pragma unroll
        for (int jj = 0; jj < 4; ++jj) wv[jj] = wcol[k * 64 + jj * 16];
#pragma unroll
        for (int r = 0; r < 8; ++r) {
            ull xv = xrow[r * 128 + k];
#pragma unroll
            for (int jj = 0; jj < 4; ++jj) fma2(acc[r][jj], xv, wv[jj]);
        }
    }

    float2 bb[4];
#pragma unroll
    for (int jj = 0; jj < 4; ++jj) {
        int j2 = jt * 64 + tx + 16 * jj;
        float2 b1 = __ldg(((const float2*)bih) + j2);
        float2 b2 = __ldg(((const float2*)bhh) + j2);
        bb[jj].x = b1.x + b2.x; bb[jj].y = b1.y + b2.y;
    }
    float2* outg = (float2*)g_xw;
#pragma unroll
    for (int r = 0; r < 8; ++r) {
        size_t row = (size_t)rt * 128 + ty * 8 + r;
#pragma unroll
        for (int jj = 0; jj < 4; ++jj) {
            float2 v = unpack2(acc[r][jj]);
            v.x += bb[jj].x; v.y += bb[jj].y;
            outg[row * 128 + jt * 64 + tx + 16 * jj] = v;
        }
    }
}

// ---------------------------------------------------------------------------
// Phase 2: recurrent scan — 64 CTAs x 256 threads, FOUR batch rows per CTA.
// W-smem crossbar cost is per-CTA-per-step, so 4 rows halves it per row.
// Thread (jq = tid&63, kq = tid>>6): j = 4jq..4jq+3, k-quarter [64kq,+64).
// W: 16 k2/j in regs (128 W regs), 8 ull2/j via per-lane LDS.128 (128KB).
// acc a[4][4] (j x row) = 32 regs. ALL register-array indices are
// compile-time constants (PUB/FIN macros with literal row per kq branch).
// Every thread finalizes row kq for its 4 columns — balanced tail.
// ---------------------------------------------------------------------------
#define NRK2 16   // k2 per j in registers (128 W regs)
#define NSU2 8    // ull2 per j in smem (16 k2)
#define NROW 4    // batch rows per CTA

__global__ void __launch_bounds__(256, 1)
scan_kernel(const float* __restrict__ Whh) {
    extern __shared__ unsigned char smem_raw[];
    ulonglong2* Wsm2 = (ulonglong2*)smem_raw;                 // [32][256] = 128KB
    float* hbuf = (float*)(smem_raw + 4 * NSU2 * 256 * 16);   // [2][4][256] = 8KB
    ulonglong2* psum2 = (ulonglong2*)(hbuf + 2048);           // [4][3][2][64] = 24KB

    const int tid = threadIdx.x;
    const int jq  = tid & 63;
    const int kq  = tid >> 6;            // 0..3
    const int j0  = jq * 4;
    const int b0  = blockIdx.x * NROW;

    // W registers: k2 idx [kq*32, kq*32+16) for each of 4 j's
    ull w[4][NRK2];
#pragma unroll
    for (int jj = 0; jj < 4; ++jj) {
        const ull* Wr = (const ull*)(Whh + (size_t)(j0 + jj) * H_) + kq * 32;
#pragma unroll
        for (int i = 0; i < NRK2; ++i) w[jj][i] = __ldg(Wr + i);
    }
    // W smem: ull2 idx [kq*16+8, kq*16+16) per j -> Wsm2[(jj*8+p)*256 + tid]
#pragma unroll
    for (int jj = 0; jj < 4; ++jj) {
        const ulonglong2* Wr2 = (const ulonglong2*)(Whh + (size_t)(j0 + jj) * H_);
#pragma unroll
        for (int p = 0; p < NSU2; ++p)
            Wsm2[(jj * NSU2 + p) * 256 + tid] = __ldg(Wr2 + kq * 16 + NRK2 / 2 + p);
    }

    // h0 = 0 (both parities)
    for (int i = tid; i < 2048; i += 256) hbuf[i] = 0.0f;
    __syncthreads();

    const ulonglong2* hb  = (const ulonglong2*)hbuf;   // [p*256 + row*64 + k4]
    const ulonglong2* wsp = Wsm2 + tid;

    // xw stream: thread finalizes row b0+kq, cols j0..j0+3
    const float4* xwp = ((const float4*)g_xw) + ((size_t)(b0 + kq) * T_) * 64 + jq;
    float4 cur = __ldg(xwp);

    for (int t = 0; t < T_; ++t) {
        const int p = t & 1;
        const ulonglong2* hbp = hb + p * 256 + kq * 16;  // + row*64 + i2

        ull a[4][NROW];
#pragma unroll
        for (int jj = 0; jj < 4; ++jj)
#pragma unroll
            for (int r = 0; r < NROW; ++r) a[jj][r] = 0ull;

        // register-W part: h ull2 slots 0..7
#pragma unroll
        for (int i2 = 0; i2 < NRK2 / 2; ++i2) {
            ulonglong2 h0 = hbp[0 * 64 + i2];
            ulonglong2 h1 = hbp[1 * 64 + i2];
            ulonglong2 h2 = hbp[2 * 64 + i2];
            ulonglong2 h3 = hbp[3 * 64 + i2];
#pragma unroll
            for (int jj = 0; jj < 4; ++jj) {
                ull wa = w[jj][2 * i2], wb = w[jj][2 * i2 + 1];
                fma2(a[jj][0], wa, h0.x); fma2(a[jj][0], wb, h0.y);
                fma2(a[jj][1], wa, h1.x); fma2(a[jj][1], wb, h1.y);
                fma2(a[jj][2], wa, h2.x); fma2(a[jj][2], wb, h2.y);
                fma2(a[jj][3], wa, h3.x); fma2(a[jj][3], wb, h3.y);
            }
        }
        // smem-W part: h ull2 slots 8..15
#pragma unroll
        for (int pp = 0; pp < NSU2; ++pp) {
            ulonglong2 h0 = hbp[0 * 64 + NRK2 / 2 + pp];
            ulonglong2 h1 = hbp[1 * 64 + NRK2 / 2 + pp];
            ulonglong2 h2 = hbp[2 * 64 + NRK2 / 2 + pp];
            ulonglong2 h3 = hbp[3 * 64 + NRK2 / 2 + pp];
#pragma unroll
            for (int jj = 0; jj < 4; ++jj) {
                ulonglong2 wv = wsp[(jj * NSU2 + pp) * 256];
                fma2(a[jj][0], wv.x, h0.x); fma2(a[jj][0], wv.y, h0.y);
                fma2(a[jj][1], wv.x, h1.x); fma2(a[jj][1], wv.y, h1.y);
                fma2(a[jj][2], wv.x, h2.x); fma2(a[jj][2], wv.y, h2.y);
                fma2(a[jj][3], wv.x, h3.x); fma2(a[jj][3], wv.y, h3.y);
            }
        }

        // publish partials (literal row/slot indices per kq branch)
#define PUB(R, S) do {                                            \
            ulonglong2 u0; u0.x = a[0][R]; u0.y = a[1][R];        \
            ulonglong2 u1; u1.x = a[2][R]; u1.y = a[3][R];        \
            psum2[(((R) * 3 + (S)) * 2 + 0) * 64 + jq] = u0;      \
            psum2[(((R) * 3 + (S)) * 2 + 1) * 64 + jq] = u1;      \
        } while (0)

        if (kq == 0)      { PUB(1, 0); PUB(2, 0); PUB(3, 0); }
        else if (kq == 1) { PUB(0, 0); PUB(2, 1); PUB(3, 1); }
        else if (kq == 2) { PUB(0, 1); PUB(1, 1); PUB(3, 2); }
        else              { PUB(0, 2); PUB(1, 2); PUB(2, 2); }
#undef PUB

        // prefetch next xw AFTER psum stores (latency absorbed by barrier)
        float4 nxt = make_float4(0.f, 0.f, 0.f, 0.f);
        if (t + 1 < T_) nxt = __ldg(xwp + (size_t)(t + 1) * 64);

        __syncthreads();

        // finalize row kq (literal accumulator indices per branch)
#define FIN(R) do {                                                       \
            float s0 = unpack_sum(a[0][R]) + cur.x;                       \
            float s1 = unpack_sum(a[1][R]) + cur.y;                       \
            float s2 = unpack_sum(a[2][R]) + cur.z;                       \
            float s3 = unpack_sum(a[3][R]) + cur.w;                       \
            _Pragma("unroll")                                             \
            for (int s = 0; s < 3; ++s) {                                 \
                ulonglong2 u0 = psum2[(((R) * 3 + s) * 2 + 0) * 64 + jq]; \
                ulonglong2 u1 = psum2[(((R) * 3 + s) * 2 + 1) * 64 + jq]; \
                s0 += unpack_sum(u0.x); s1 += unpack_sum(u0.y);           \
                s2 += unpack_sum(u1.x); s3 += unpack_sum(u1.y);           \
            }                                                             \
            float4 hv;                                                    \
            hv.x = ftanh(s0); hv.y = ftanh(s1);                           \
            hv.z = ftanh(s2); hv.w = ftanh(s3);                           \
            ((float4*)hbuf)[((p ^ 1) * 4 + (R)) * 64 + jq] = hv;          \
            if (t == T_ - 1)                                              \
                ((float4*)g_h)[(b0 + (R)) * 64 + jq] = hv;                \
        } while (0)

        if (kq == 0)      FIN(0);
        else if (kq == 1) FIN(1);
        else if (kq == 2) FIN(2);
        else              FIN(3);
#undef FIN

        cur = nxt;
        __syncthreads();
    }
}

// ---------------------------------------------------------------------------
// Phase 3: out[b] = g_h[b,:] . fc_w + fc_b
// ---------------------------------------------------------------------------
__global__ void __launch_bounds__(256)
fc_kernel(const float* __restrict__ fcw, const float* __restrict__ fcb,
          float* __restrict__ out) {
    const int b = blockIdx.x, tid = threadIdx.x;
    float v = g_h[b * H_ + tid] * __ldg(fcw + tid);
#pragma unroll
    for (int o = 16; o; o >>= 1) v += __shfl_down_sync(0xffffffffu, v, o);
    __shared__ float red[8];
    if ((tid & 31) == 0) red[tid >> 5] = v;
    __syncthreads();
    if (tid == 0) {
        float s = 0.f;
#pragma unroll
        for (int i = 0; i < 8; ++i) s += red[i];
        out[b] = s + __ldg(fcb);
    }
}

// ---------------------------------------------------------------------------
extern "C" void kernel_launch(void* const* d_in, const int* in_sizes, int n_in,
                              void* d_out, int out_size) {
    (void)in_sizes; (void)n_in; (void)out_size;
    const float* x   = (const float*)d_in[0];
    const float* Wih = (const float*)d_in[1];
    const float* Whh = (const float*)d_in[2];
    const float* bih = (const float*)d_in[3];
    const float* bhh = (const float*)d_in[4];
    const float* fcw = (const float*)d_in[5];
    const float* fcb = (const float*)d_in[6];
    float* out = (float*)d_out;

    const int XW_SMEM   = 128 * 128 * 8 + 128 * 64 * 8;   // 192KB
    const int SCAN_SMEM = 4 * NSU2 * 256 * 16             // 128KB W
                        + 2048 * 4                        // 8KB h
                        + 4 * 3 * 2 * 64 * 16;            // 24KB psum

    cudaFuncSetAttribute(xw_kernel, cudaFuncAttributeMaxDynamicSharedMemorySize, XW_SMEM);
    cudaFuncSetAttribute(scan_kernel, cudaFuncAttributeMaxDynamicSharedMemorySize, SCAN_SMEM);

    wpack_kernel<<<64, 256>>>(Wih);
    xw_kernel<<<2048, 256, XW_SMEM>>>(x, bih, bhh);
    scan_kernel<<<64, 256, SCAN_SMEM>>>(Whh);
    fc_kernel<<<256, 256>>>(fcw, fcb, out);
}

// round 14
// speedup vs baseline: 1.4906x; 1.4906x over previous
#include <cuda_runtime.h>
#include <cstdint>
#include <math.h>

#define B_ 256
#define T_ 512
#define I_ 128
#define H_ 256

typedef unsigned long long ull;

// Scratch (static device globals — no dynamic allocation allowed).
__device__ float g_xw[(size_t)B_ * T_ * H_];   // [B][T][H] input projection + bias
__device__ float g_h[B_ * H_];                 // final hidden state
__device__ ull   g_wpack[I_ * (H_ / 2)];       // W_ih packed: [k][j2] = {W[2j2][k], W[2j2+1][k]}

// ---------------------------------------------------------------------------
// helpers
// ---------------------------------------------------------------------------
__device__ __forceinline__ void fma2(ull& acc, ull a, ull b) {
    asm("fma.rn.f32x2 %0, %1, %2, %0;" : "+l"(acc) : "l"(a), "l"(b));
}

__device__ __forceinline__ float unpack_sum(ull v) {
    float lo, hi;
    asm("mov.b64 {%0,%1}, %2;" : "=f"(lo), "=f"(hi) : "l"(v));
    return lo + hi;
}

__device__ __forceinline__ float2 unpack2(ull v) {
    float2 r;
    asm("mov.b64 {%0,%1}, %2;" : "=f"(r.x), "=f"(r.y) : "l"(v));
    return r;
}

__device__ __forceinline__ ull pack2(float a, float b) {
    ull u;
    asm("mov.b64 %0,{%1,%2};" : "=l"(u) : "f"(a), "f"(b));
    return u;
}

__device__ __forceinline__ ull dup1(float a) {
    ull u;
    asm("mov.b64 %0,{%1,%1};" : "=l"(u) : "f"(a));
    return u;
}

// tanh(x) = 1 - 2/(e^{2x}+1) via ex2/rcp approx. Branch-free, inf-safe.
__device__ __forceinline__ float ftanh(float x) {
    float e;
    asm("ex2.approx.f32 %0, %1;" : "=f"(e) : "f"(x * 2.8853900817779268f));
    float r;
    asm("rcp.approx.f32 %0, %1;" : "=f"(r) : "f"(e + 1.0f));
    return fmaf(-2.0f, r, 1.0f);
}

// ---------------------------------------------------------------------------
// Phase 0: pack W_ih k-major with j-pairs
// ---------------------------------------------------------------------------
__global__ void __launch_bounds__(256)
wpack_kernel(const float* __restrict__ Wih) {
    int t = blockIdx.x * 256 + threadIdx.x;   // 16384 total
    int j2 = t & 127, k = t >> 7;
    float a = __ldg(Wih + (2 * j2) * I_ + k);
    float b = __ldg(Wih + (2 * j2 + 1) * I_ + k);
    g_wpack[k * 128 + j2] = pack2(a, b);
}

// ---------------------------------------------------------------------------
// Phase 1: register-tiled f32x2 GEMM (unchanged)
// ---------------------------------------------------------------------------
__global__ void __launch_bounds__(256, 1)
xw_kernel(const float* __restrict__ x,
          const float* __restrict__ bih, const float* __restrict__ bhh) {
    extern __shared__ unsigned char smem_raw[];
    ull* xs = (ull*)smem_raw;                       // [r][k] dup, 128KB
    ull* ws = (ull*)(smem_raw + 128 * 128 * 8);     // [k][j2l], 64KB

    const int tid = threadIdx.x;
    const int jt  = blockIdx.x & 1;
    const int rt  = blockIdx.x >> 1;
    const int tx  = tid & 15;
    const int ty  = tid >> 4;

    {
        const float4* xg = (const float4*)(x + (size_t)rt * 128 * I_);
        for (int i = 0; i < 16; ++i) {
            int lin = tid + i * 256;
            float4 v = __ldg(xg + lin);
            int r = lin >> 5, kc = lin & 31;
            ulonglong2* d = (ulonglong2*)(xs + r * 128 + kc * 4);
            ulonglong2 u0; u0.x = dup1(v.x); u0.y = dup1(v.y);
            ulonglong2 u1; u1.x = dup1(v.z); u1.y = dup1(v.w);
            d[0] = u0; d[1] = u1;
        }
    }
    {
        const ulonglong2* wg = (const ulonglong2*)g_wpack;
        ulonglong2* wd = (ulonglong2*)ws;
        for (int i = 0; i < 16; ++i) {
            int lin = tid + i * 256;
            int k = lin >> 5, c = lin & 31;
            wd[k * 32 + c] = __ldg(wg + k * 64 + jt * 32 + c);
        }
    }
    __syncthreads();

    ull acc[8][4];
#pragma unroll
    for (int r = 0; r < 8; ++r)
#pragma unroll
        for (int j = 0; j < 4; ++j) acc[r][j] = 0ull;

    const ull* xrow = xs + (ty * 8) * 128;
    const ull* wcol = ws + tx;

#pragma unroll 4
    for (int k = 0; k < 128; ++k) {
        ull wv[4];
#pragma unroll
        for (int jj = 0; jj < 4; ++jj) wv[jj] = wcol[k * 64 + jj * 16];
#pragma unroll
        for (int r = 0; r < 8; ++r) {
            ull xv = xrow[r * 128 + k];
#pragma unroll
            for (int jj = 0; jj < 4; ++jj) fma2(acc[r][jj], xv, wv[jj]);
        }
    }

    float2 bb[4];
#pragma unroll
    for (int jj = 0; jj < 4; ++jj) {
        int j2 = jt * 64 + tx + 16 * jj;
        float2 b1 = __ldg(((const float2*)bih) + j2);
        float2 b2 = __ldg(((const float2*)bhh) + j2);
        bb[jj].x = b1.x + b2.x; bb[jj].y = b1.y + b2.y;
    }
    float2* outg = (float2*)g_xw;
#pragma unroll
    for (int r = 0; r < 8; ++r) {
        size_t row = (size_t)rt * 128 + ty * 8 + r;
#pragma unroll
        for (int jj = 0; jj < 4; ++jj) {
            float2 v = unpack2(acc[r][jj]);
            v.x += bb[jj].x; v.y += bb[jj].y;
            outg[row * 128 + jt * 64 + tx + 16 * jj] = v;
        }
    }
}

// ---------------------------------------------------------------------------
// Phase 2: recurrent scan — EXACT R7 structure (proven 865us), with the one
// latent defect fixed: the finalize previously indexed the accumulator
// register array with runtime kq (a[jj][kq]) — a local-memory demotion
// hazard. Now dispatched via FIN(R) with literal indices under
// if (kq==0/1) branches. No other change.
// 128 CTAs x 256 threads, 2 batch rows per CTA.
// Thread (jq = tid&63, kq = tid>>6): j = 4jq..4jq+3, k-quarter [64kq,+64).
// W: 20 k2/j in regs (160 W regs — proven), 12 k2/j via per-lane LDS.128.
// ---------------------------------------------------------------------------
#define NRK2 20   // k2 per j in registers
#define NSU2 6    // ull2 per j in smem (12 k2)

__global__ void __launch_bounds__(256, 1)
scan_kernel(const float* __restrict__ Whh) {
    extern __shared__ unsigned char smem_raw[];
    ulonglong2* Wsm2 = (ulonglong2*)smem_raw;                 // [24][256] = 96KB
    float* hbuf = (float*)(smem_raw + 4 * NSU2 * 256 * 16);   // [2][2][256] = 4KB
    ulonglong2* psum2 = (ulonglong2*)(hbuf + 1024);           // [2][3][2][64] = 12KB

    const int tid = threadIdx.x;
    const int jq  = tid & 63;
    const int kq  = tid >> 6;            // 0..3
    const int j0  = jq * 4;
    const int b0  = blockIdx.x * 2;

    // W registers: k2 idx [kq*32, kq*32+20) for each of 4 j's
    ull w[4][NRK2];
#pragma unroll
    for (int jj = 0; jj < 4; ++jj) {
        const ull* Wr = (const ull*)(Whh + (size_t)(j0 + jj) * H_) + kq * 32;
#pragma unroll
        for (int i = 0; i < NRK2; ++i) w[jj][i] = __ldg(Wr + i);
    }
    // W smem: ull2 idx [kq*16+10, kq*16+16) per j -> Wsm2[(jj*6+p)*256 + tid]
#pragma unroll
    for (int jj = 0; jj < 4; ++jj) {
        const ulonglong2* Wr2 = (const ulonglong2*)(Whh + (size_t)(j0 + jj) * H_);
#pragma unroll
        for (int p = 0; p < NSU2; ++p)
            Wsm2[(jj * NSU2 + p) * 256 + tid] = __ldg(Wr2 + kq * 16 + 10 + p);
    }

    // h0 = 0 (both parities)
    for (int i = tid; i < 1024; i += 256) hbuf[i] = 0.0f;
    __syncthreads();

    const ulonglong2* hb  = (const ulonglong2*)hbuf;   // [(p*2+row)*64 + k4]
    const ulonglong2* wsp = Wsm2 + tid;

    // xw stream: finalizer (kq<2) covers row b0+kq, cols j0..j0+3
    const float4* xwp = ((const float4*)g_xw) + ((size_t)(b0 + kq) * T_) * 64 + jq;
    float4 cur = make_float4(0.f, 0.f, 0.f, 0.f);
    if (kq < 2) cur = __ldg(xwp);

    for (int t = 0; t < T_; ++t) {
        const int p = t & 1;
        const ulonglong2* h0p = hb + (p * 2 + 0) * 64 + kq * 16;
        const ulonglong2* h1p = hb + (p * 2 + 1) * 64 + kq * 16;

        ull a[4][2];
#pragma unroll
        for (int jj = 0; jj < 4; ++jj) { a[jj][0] = 0ull; a[jj][1] = 0ull; }

        // register-W part: h ull2 idx 0..9
#pragma unroll
        for (int i2 = 0; i2 < NRK2 / 2; ++i2) {
            ulonglong2 h0 = h0p[i2], h1 = h1p[i2];
#pragma unroll
            for (int jj = 0; jj < 4; ++jj) {
                fma2(a[jj][0], w[jj][2 * i2], h0.x); fma2(a[jj][0], w[jj][2 * i2 + 1], h0.y);
                fma2(a[jj][1], w[jj][2 * i2], h1.x); fma2(a[jj][1], w[jj][2 * i2 + 1], h1.y);
            }
        }
        // smem-W part: h ull2 idx 10..15
#pragma unroll
        for (int pp = 0; pp < NSU2; ++pp) {
            ulonglong2 h0 = h0p[NRK2 / 2 + pp], h1 = h1p[NRK2 / 2 + pp];
#pragma unroll
            for (int jj = 0; jj < 4; ++jj) {
                ulonglong2 wv = wsp[(jj * NSU2 + pp) * 256];
                fma2(a[jj][0], wv.x, h0.x); fma2(a[jj][0], wv.y, h0.y);
                fma2(a[jj][1], wv.x, h1.x); fma2(a[jj][1], wv.y, h1.y);
            }
        }

        // prefetch next xw
        float4 nxt = make_float4(0.f, 0.f, 0.f, 0.f);
        if (kq < 2 && t + 1 < T_) nxt = __ldg(xwp + (size_t)(t + 1) * 64);

        // publish partials for rows I don't finalize (literal indices per kq)
        {
            if (kq == 0) {
                ulonglong2 u0; u0.x = a[0][1]; u0.y = a[1][1];
                ulonglong2 u1; u1.x = a[2][1]; u1.y = a[3][1];
                psum2[((1 * 3 + 0) * 2 + 0) * 64 + jq] = u0;
                psum2[((1 * 3 + 0) * 2 + 1) * 64 + jq] = u1;
            } else if (kq == 1) {
                ulonglong2 u0; u0.x = a[0][0]; u0.y = a[1][0];
                ulonglong2 u1; u1.x = a[2][0]; u1.y = a[3][0];
                psum2[((0 * 3 + 0) * 2 + 0) * 64 + jq] = u0;
                psum2[((0 * 3 + 0) * 2 + 1) * 64 + jq] = u1;
            } else {
                int s = kq - 1;  // 1 or 2 (smem index — runtime OK)
#pragma unroll
                for (int r = 0; r < 2; ++r) {
                    ulonglong2 u0; u0.x = a[0][r]; u0.y = a[1][r];
                    ulonglong2 u1; u1.x = a[2][r]; u1.y = a[3][r];
                    psum2[((r * 3 + s) * 2 + 0) * 64 + jq] = u0;
                    psum2[((r * 3 + s) * 2 + 1) * 64 + jq] = u1;
                }
            }
        }

        __syncthreads();

        // finalize with LITERAL accumulator indices (no runtime reg-indexing)
#define FIN(R) do {                                                       \
            float s0 = unpack_sum(a[0][R]) + cur.x;                       \
            float s1 = unpack_sum(a[1][R]) + cur.y;                       \
            float s2 = unpack_sum(a[2][R]) + cur.z;                       \
            float s3 = unpack_sum(a[3][R]) + cur.w;                       \
            _Pragma("unroll")                                             \
            for (int s = 0; s < 3; ++s) {                                 \
                ulonglong2 u0 = psum2[(((R) * 3 + s) * 2 + 0) * 64 + jq]; \
                ulonglong2 u1 = psum2[(((R) * 3 + s) * 2 + 1) * 64 + jq]; \
                s0 += unpack_sum(u0.x); s1 += unpack_sum(u0.y);           \
                s2 += unpack_sum(u1.x); s3 += unpack_sum(u1.y);           \
            }                                                             \
            float4 hv;                                                    \
            hv.x = ftanh(s0); hv.y = ftanh(s1);                           \
            hv.z = ftanh(s2); hv.w = ftanh(s3);                           \
            ((float4*)hbuf)[(((p ^ 1) * 2) + (R)) * 64 + jq] = hv;        \
            if (t == T_ - 1)                                              \
                ((float4*)g_h)[(b0 + (R)) * 64 + jq] = hv;                \
        } while (0)

        if (kq == 0)      FIN(0);
        else if (kq == 1) FIN(1);
#undef FIN

        if (kq < 2) cur = nxt;
        __syncthreads();
    }
}

// ---------------------------------------------------------------------------
// Phase 3: out[b] = g_h[b,:] . fc_w + fc_b
// ---------------------------------------------------------------------------
__global__ void __launch_bounds__(256)
fc_kernel(const float* __restrict__ fcw, const float* __restrict__ fcb,
          float* __restrict__ out) {
    const int b = blockIdx.x, tid = threadIdx.x;
    float v = g_h[b * H_ + tid] * __ldg(fcw + tid);
#pragma unroll
    for (int o = 16; o; o >>= 1) v += __shfl_down_sync(0xffffffffu, v, o);
    __shared__ float red[8];
    if ((tid & 31) == 0) red[tid >> 5] = v;
    __syncthreads();
    if (tid == 0) {
        float s = 0.f;
#pragma unroll
        for (int i = 0; i < 8; ++i) s += red[i];
        out[b] = s + __ldg(fcb);
    }
}

// ---------------------------------------------------------------------------
extern "C" void kernel_launch(void* const* d_in, const int* in_sizes, int n_in,
                              void* d_out, int out_size) {
    (void)in_sizes; (void)n_in; (void)out_size;
    const float* x   = (const float*)d_in[0];
    const float* Wih = (const float*)d_in[1];
    const float* Whh = (const float*)d_in[2];
    const float* bih = (const float*)d_in[3];
    const float* bhh = (const float*)d_in[4];
    const float* fcw = (const float*)d_in[5];
    const float* fcb = (const float*)d_in[6];
    float* out = (float*)d_out;

    const int XW_SMEM   = 128 * 128 * 8 + 128 * 64 * 8;                          // 192KB
    const int SCAN_SMEM = 4 * NSU2 * 256 * 16 + 1024 * 4 + 2 * 3 * 2 * 64 * 16;  // 112KB

    cudaFuncSetAttribute(xw_kernel, cudaFuncAttributeMaxDynamicSharedMemorySize, XW_SMEM);
    cudaFuncSetAttribute(scan_kernel, cudaFuncAttributeMaxDynamicSharedMemorySize, SCAN_SMEM);

    wpack_kernel<<<64, 256>>>(Wih);
    xw_kernel<<<2048, 256, XW_SMEM>>>(x, bih, bhh);
    scan_kernel<<<128, 256, SCAN_SMEM>>>(Whh);
    fc_kernel<<<256, 256>>>(fcw, fcb, out);
}

// round 15
// speedup vs baseline: 1.5437x; 1.0356x over previous
#include <cuda_runtime.h>
#include <cstdint>
#include <math.h>

#define B_ 256
#define T_ 512
#define I_ 128
#define H_ 256

typedef unsigned long long ull;

// Scratch (static device globals — no dynamic allocation allowed).
__device__ float g_xw[(size_t)B_ * T_ * H_];   // [B][T][H] input projection + bias
__device__ float g_h[B_ * H_];                 // final hidden state
__device__ ull   g_wpack[I_ * (H_ / 2)];       // W_ih packed: [k][j2] = {W[2j2][k], W[2j2+1][k]}

// ---------------------------------------------------------------------------
// helpers
// ---------------------------------------------------------------------------
__device__ __forceinline__ void fma2(ull& acc, ull a, ull b) {
    asm("fma.rn.f32x2 %0, %1, %2, %0;" : "+l"(acc) : "l"(a), "l"(b));
}

__device__ __forceinline__ float unpack_sum(ull v) {
    float lo, hi;
    asm("mov.b64 {%0,%1}, %2;" : "=f"(lo), "=f"(hi) : "l"(v));
    return lo + hi;
}

__device__ __forceinline__ float2 unpack2(ull v) {
    float2 r;
    asm("mov.b64 {%0,%1}, %2;" : "=f"(r.x), "=f"(r.y) : "l"(v));
    return r;
}

__device__ __forceinline__ ull pack2(float a, float b) {
    ull u;
    asm("mov.b64 %0,{%1,%2};" : "=l"(u) : "f"(a), "f"(b));
    return u;
}

__device__ __forceinline__ ull dup1(float a) {
    ull u;
    asm("mov.b64 %0,{%1,%1};" : "=l"(u) : "f"(a));
    return u;
}

// tanh(x) = 1 - 2/(e^{2x}+1) via ex2/rcp approx. Branch-free, inf-safe.
__device__ __forceinline__ float ftanh(float x) {
    float e;
    asm("ex2.approx.f32 %0, %1;" : "=f"(e) : "f"(x * 2.8853900817779268f));
    float r;
    asm("rcp.approx.f32 %0, %1;" : "=f"(r) : "f"(e + 1.0f));
    return fmaf(-2.0f, r, 1.0f);
}

// ---------------------------------------------------------------------------
// Phase 0: pack W_ih k-major with j-pairs
// ---------------------------------------------------------------------------
__global__ void __launch_bounds__(256)
wpack_kernel(const float* __restrict__ Wih) {
    int t = blockIdx.x * 256 + threadIdx.x;   // 16384 total
    int j2 = t & 127, k = t >> 7;
    float a = __ldg(Wih + (2 * j2) * I_ + k);
    float b = __ldg(Wih + (2 * j2 + 1) * I_ + k);
    g_wpack[k * 128 + j2] = pack2(a, b);
}

// ---------------------------------------------------------------------------
// Phase 1: register-tiled f32x2 GEMM (unchanged — ~80% of f32x2 ceiling)
// ---------------------------------------------------------------------------
__global__ void __launch_bounds__(256, 1)
xw_kernel(const float* __restrict__ x,
          const float* __restrict__ bih, const float* __restrict__ bhh) {
    extern __shared__ unsigned char smem_raw[];
    ull* xs = (ull*)smem_raw;                       // [r][k] dup, 128KB
    ull* ws = (ull*)(smem_raw + 128 * 128 * 8);     // [k][j2l], 64KB

    const int tid = threadIdx.x;
    const int jt  = blockIdx.x & 1;
    const int rt  = blockIdx.x >> 1;
    const int tx  = tid & 15;
    const int ty  = tid >> 4;

    {
        const float4* xg = (const float4*)(x + (size_t)rt * 128 * I_);
        for (int i = 0; i < 16; ++i) {
            int lin = tid + i * 256;
            float4 v = __ldg(xg + lin);
            int r = lin >> 5, kc = lin & 31;
            ulonglong2* d = (ulonglong2*)(xs + r * 128 + kc * 4);
            ulonglong2 u0; u0.x = dup1(v.x); u0.y = dup1(v.y);
            ulonglong2 u1; u1.x = dup1(v.z); u1.y = dup1(v.w);
            d[0] = u0; d[1] = u1;
        }
    }
    {
        const ulonglong2* wg = (const ulonglong2*)g_wpack;
        ulonglong2* wd = (ulonglong2*)ws;
        for (int i = 0; i < 16; ++i) {
            int lin = tid + i * 256;
            int k = lin >> 5, c = lin & 31;
            wd[k * 32 + c] = __ldg(wg + k * 64 + jt * 32 + c);
        }
    }
    __syncthreads();

    ull acc[8][4];
#pragma unroll
    for (int r = 0; r < 8; ++r)
#pragma unroll
        for (int j = 0; j < 4; ++j) acc[r][j] = 0ull;

    const ull* xrow = xs + (ty * 8) * 128;
    const ull* wcol = ws + tx;

#pragma unroll 4
    for (int k = 0; k < 128; ++k) {
        ull wv[4];
#pragma unroll
        for (int jj = 0; jj < 4; ++jj) wv[jj] = wcol[k * 64 + jj * 16];
#pragma unroll
        for (int r = 0; r < 8; ++r) {
            ull xv = xrow[r * 128 + k];
#pragma unroll
            for (int jj = 0; jj < 4; ++jj) fma2(acc[r][jj], xv, wv[jj]);
        }
    }

    float2 bb[4];
#pragma unroll
    for (int jj = 0; jj < 4; ++jj) {
        int j2 = jt * 64 + tx + 16 * jj;
        float2 b1 = __ldg(((const float2*)bih) + j2);
        float2 b2 = __ldg(((const float2*)bhh) + j2);
        bb[jj].x = b1.x + b2.x; bb[jj].y = b1.y + b2.y;
    }
    float2* outg = (float2*)g_xw;
#pragma unroll
    for (int r = 0; r < 8; ++r) {
        size_t row = (size_t)rt * 128 + ty * 8 + r;
#pragma unroll
        for (int jj = 0; jj < 4; ++jj) {
            float2 v = unpack2(acc[r][jj]);
            v.x += bb[jj].x; v.y += bb[jj].y;
            outg[row * 128 + jt * 64 + tx + 16 * jj] = v;
        }
    }
}

// ---------------------------------------------------------------------------
// Phase 2: recurrent scan — R13 structure (literal-index finalize, proven
// 811us). Single knob: NRK2 22 / NSU2 5 — re-probing the W-register
// boundary now that the runtime-index demotion is fixed (pressure dropped).
// 128 CTAs x 256 threads, 2 batch rows per CTA.
// Thread (jq = tid&63, kq = tid>>6): j = 4jq..4jq+3, k-quarter [64kq,+64).
// ---------------------------------------------------------------------------
#define NRK2 22   // k2 per j in registers (176 W regs — re-probe post-fix)
#define NSU2 5    // ull2 per j in smem (10 k2)

__global__ void __launch_bounds__(256, 1)
scan_kernel(const float* __restrict__ Whh) {
    extern __shared__ unsigned char smem_raw[];
    ulonglong2* Wsm2 = (ulonglong2*)smem_raw;                 // [20][256] = 80KB
    float* hbuf = (float*)(smem_raw + 4 * NSU2 * 256 * 16);   // [2][2][256] = 4KB
    ulonglong2* psum2 = (ulonglong2*)(hbuf + 1024);           // [2][3][2][64] = 12KB

    const int tid = threadIdx.x;
    const int jq  = tid & 63;
    const int kq  = tid >> 6;            // 0..3
    const int j0  = jq * 4;
    const int b0  = blockIdx.x * 2;

    // W registers: k2 idx [kq*32, kq*32+22) for each of 4 j's
    ull w[4][NRK2];
#pragma unroll
    for (int jj = 0; jj < 4; ++jj) {
        const ull* Wr = (const ull*)(Whh + (size_t)(j0 + jj) * H_) + kq * 32;
#pragma unroll
        for (int i = 0; i < NRK2; ++i) w[jj][i] = __ldg(Wr + i);
    }
    // W smem: ull2 idx [kq*16+11, kq*16+16) per j -> Wsm2[(jj*5+p)*256 + tid]
#pragma unroll
    for (int jj = 0; jj < 4; ++jj) {
        const ulonglong2* Wr2 = (const ulonglong2*)(Whh + (size_t)(j0 + jj) * H_);
#pragma unroll
        for (int p = 0; p < NSU2; ++p)
            Wsm2[(jj * NSU2 + p) * 256 + tid] = __ldg(Wr2 + kq * 16 + NRK2 / 2 + p);
    }

    // h0 = 0 (both parities)
    for (int i = tid; i < 1024; i += 256) hbuf[i] = 0.0f;
    __syncthreads();

    const ulonglong2* hb  = (const ulonglong2*)hbuf;   // [(p*2+row)*64 + k4]
    const ulonglong2* wsp = Wsm2 + tid;

    // xw stream: finalizer (kq<2) covers row b0+kq, cols j0..j0+3
    const float4* xwp = ((const float4*)g_xw) + ((size_t)(b0 + kq) * T_) * 64 + jq;
    float4 cur = make_float4(0.f, 0.f, 0.f, 0.f);
    if (kq < 2) cur = __ldg(xwp);

    for (int t = 0; t < T_; ++t) {
        const int p = t & 1;
        const ulonglong2* h0p = hb + (p * 2 + 0) * 64 + kq * 16;
        const ulonglong2* h1p = hb + (p * 2 + 1) * 64 + kq * 16;

        ull a[4][2];
#pragma unroll
        for (int jj = 0; jj < 4; ++jj) { a[jj][0] = 0ull; a[jj][1] = 0ull; }

        // register-W part: h ull2 idx 0..10
#pragma unroll
        for (int i2 = 0; i2 < NRK2 / 2; ++i2) {
            ulonglong2 h0 = h0p[i2], h1 = h1p[i2];
#pragma unroll
            for (int jj = 0; jj < 4; ++jj) {
                fma2(a[jj][0], w[jj][2 * i2], h0.x); fma2(a[jj][0], w[jj][2 * i2 + 1], h0.y);
                fma2(a[jj][1], w[jj][2 * i2], h1.x); fma2(a[jj][1], w[jj][2 * i2 + 1], h1.y);
            }
        }
        // smem-W part: h ull2 idx 11..15
#pragma unroll
        for (int pp = 0; pp < NSU2; ++pp) {
            ulonglong2 h0 = h0p[NRK2 / 2 + pp], h1 = h1p[NRK2 / 2 + pp];
#pragma unroll
            for (int jj = 0; jj < 4; ++jj) {
                ulonglong2 wv = wsp[(jj * NSU2 + pp) * 256];
                fma2(a[jj][0], wv.x, h0.x); fma2(a[jj][0], wv.y, h0.y);
                fma2(a[jj][1], wv.x, h1.x); fma2(a[jj][1], wv.y, h1.y);
            }
        }

        // prefetch next xw
        float4 nxt = make_float4(0.f, 0.f, 0.f, 0.f);
        if (kq < 2 && t + 1 < T_) nxt = __ldg(xwp + (size_t)(t + 1) * 64);

        // publish partials for rows I don't finalize (literal indices per kq)
        {
            if (kq == 0) {
                ulonglong2 u0; u0.x = a[0][1]; u0.y = a[1][1];
                ulonglong2 u1; u1.x = a[2][1]; u1.y = a[3][1];
                psum2[((1 * 3 + 0) * 2 + 0) * 64 + jq] = u0;
                psum2[((1 * 3 + 0) * 2 + 1) * 64 + jq] = u1;
            } else if (kq == 1) {
                ulonglong2 u0; u0.x = a[0][0]; u0.y = a[1][0];
                ulonglong2 u1; u1.x = a[2][0]; u1.y = a[3][0];
                psum2[((0 * 3 + 0) * 2 + 0) * 64 + jq] = u0;
                psum2[((0 * 3 + 0) * 2 + 1) * 64 + jq] = u1;
            } else {
                int s = kq - 1;  // 1 or 2 (smem index — runtime OK)
#pragma unroll
                for (int r = 0; r < 2; ++r) {
                    ulonglong2 u0; u0.x = a[0][r]; u0.y = a[1][r];
                    ulonglong2 u1; u1.x = a[2][r]; u1.y = a[3][r];
                    psum2[((r * 3 + s) * 2 + 0) * 64 + jq] = u0;
                    psum2[((r * 3 + s) * 2 + 1) * 64 + jq] = u1;
                }
            }
        }

        __syncthreads();

        // finalize with LITERAL accumulator indices (no runtime reg-indexing)
#define FIN(R) do {                                                       \
            float s0 = unpack_sum(a[0][R]) + cur.x;                       \
            float s1 = unpack_sum(a[1][R]) + cur.y;                       \
            float s2 = unpack_sum(a[2][R]) + cur.z;                       \
            float s3 = unpack_sum(a[3][R]) + cur.w;                       \
            _Pragma("unroll")                                             \
            for (int s = 0; s < 3; ++s) {                                 \
                ulonglong2 u0 = psum2[(((R) * 3 + s) * 2 + 0) * 64 + jq]; \
                ulonglong2 u1 = psum2[(((R) * 3 + s) * 2 + 1) * 64 + jq]; \
                s0 += unpack_sum(u0.x); s1 += unpack_sum(u0.y);           \
                s2 += unpack_sum(u1.x); s3 += unpack_sum(u1.y);           \
            }                                                             \
            float4 hv;                                                    \
            hv.x = ftanh(s0); hv.y = ftanh(s1);                           \
            hv.z = ftanh(s2); hv.w = ftanh(s3);                           \
            ((float4*)hbuf)[(((p ^ 1) * 2) + (R)) * 64 + jq] = hv;        \
            if (t == T_ - 1)                                              \
                ((float4*)g_h)[(b0 + (R)) * 64 + jq] = hv;                \
        } while (0)

        if (kq == 0)      FIN(0);
        else if (kq == 1) FIN(1);
#undef FIN

        if (kq < 2) cur = nxt;
        __syncthreads();
    }
}

// ---------------------------------------------------------------------------
// Phase 3: out[b] = g_h[b,:] . fc_w + fc_b
// ---------------------------------------------------------------------------
__global__ void __launch_bounds__(256)
fc_kernel(const float* __restrict__ fcw, const float* __restrict__ fcb,
          float* __restrict__ out) {
    const int b = blockIdx.x, tid = threadIdx.x;
    float v = g_h[b * H_ + tid] * __ldg(fcw + tid);
#pragma unroll
    for (int o = 16; o; o >>= 1) v += __shfl_down_sync(0xffffffffu, v, o);
    __shared__ float red[8];
    if ((tid & 31) == 0) red[tid >> 5] = v;
    __syncthreads();
    if (tid == 0) {
        float s = 0.f;
#pragma unroll
        for (int i = 0; i < 8; ++i) s += red[i];
        out[b] = s + __ldg(fcb);
    }
}

// ---------------------------------------------------------------------------
extern "C" void kernel_launch(void* const* d_in, const int* in_sizes, int n_in,
                              void* d_out, int out_size) {
    (void)in_sizes; (void)n_in; (void)out_size;
    const float* x   = (const float*)d_in[0];
    const float* Wih = (const float*)d_in[1];
    const float* Whh = (const float*)d_in[2];
    const float* bih = (const float*)d_in[3];
    const float* bhh = (const float*)d_in[4];
    const float* fcw = (const float*)d_in[5];
    const float* fcb = (const float*)d_in[6];
    float* out = (float*)d_out;

    const int XW_SMEM   = 128 * 128 * 8 + 128 * 64 * 8;                          // 192KB
    const int SCAN_SMEM = 4 * NSU2 * 256 * 16 + 1024 * 4 + 2 * 3 * 2 * 64 * 16;  // 96KB

    cudaFuncSetAttribute(xw_kernel, cudaFuncAttributeMaxDynamicSharedMemorySize, XW_SMEM);
    cudaFuncSetAttribute(scan_kernel, cudaFuncAttributeMaxDynamicSharedMemorySize, SCAN_SMEM);

    wpack_kernel<<<64, 256>>>(Wih);
    xw_kernel<<<2048, 256, XW_SMEM>>>(x, bih, bhh);
    scan_kernel<<<128, 256, SCAN_SMEM>>>(Whh);
    fc_kernel<<<256, 256>>>(fcw, fcb, out);
}